// round 12
// baseline (speedup 1.0000x reference)
#include <cuda_runtime.h>
#include <math.h>

#define B_ROWS 65536
#define C_CLS  1000
#define C4     250        // 1000 floats = 250 float4 per row
#define BETA_F 3.0f
#define LOG2E_F 1.4426950408889634f
#define DOT_BLOCKS 256
#define ROWS_BLOCKS 888   // 6 blocks/SM * 148 SMs -> single persistent wave
#define ROWS_WARPS (ROWS_BLOCKS * 8)

// ---- scratch (no allocations allowed; zero-initialized at module load) ----
__device__ __align__(16) int    g_counts[C_CLS * C_CLS];
__device__ __align__(16) float  g_cmn[C_CLS * C_CLS];   // (cost+counts)*scale
__device__ __align__(16) float2 g_pair[B_ROWS];         // {glp, bits(t*1000+p)}
__device__ float  g_partial[DOT_BLOCKS];
__device__ unsigned int g_done;                          // reset by k_dot last block

// ---------------------------------------------------------------------------
// k1: PERSISTENT one-warp-per-row, SINGLE-PASS online softmax.
// Each lane keeps running (m, am, s): on a new quad max, rescale s by
// exp2((m_old-m_new)*log2e) and take the first in-quad index of the max;
// otherwise just accumulate exp2 terms. One streamed (.cs) read per element
// -> half the LDG/L1 traffic of the two-pass version. Cross-lane merge is
// the online-softmax combine with strict-> / min-index tiebreak (= first-
// index jnp.argmax on exact bit-equal values).
// ---------------------------------------------------------------------------
__global__ __launch_bounds__(256, 6) void k_rows(
    const float* __restrict__ outp, const void* __restrict__ tgt)
{
    int tid   = threadIdx.x;
    int lane  = tid & 31;
    int gwarp = (blockIdx.x * 256 + tid) >> 5;

    // Per-warp dtype detect (hoisted): int64 targets in [0,1000) have
    // all-zero odd 32-bit words. Scan odd words of the first 64 entries.
    const int* tw = (const int*)tgt;
    int nz = tw[4 * lane + 1] | tw[4 * lane + 3];
    int is64 = (__ballot_sync(0xffffffffu, nz != 0) == 0u);
    const long long* t64 = (const long long*)tgt;
    const int*       t32 = (const int*)tgt;

    bool tail = (lane < (C4 - 224));            // last quad valid?

    for (int row_i = gwarp; row_i < B_ROWS; row_i += ROWS_WARPS) {
        const float*  row = outp + (size_t)row_i * C_CLS;
        const float4* rp  = (const float4*)row;

        // Prefetch target index + target logit on lane 0 (overlaps loads).
        int   t  = 0;
        float xt = 0.0f;
        if (lane == 0) {
            t  = is64 ? (int)t64[row_i] : t32[row_i];
            xt = row[t];
        }

        // Online pass: running max m, argmax am, scaled sums s0/s1.
        float m  = -INFINITY;
        float nml = -INFINITY;                   // -m * log2e
        int   am = 0x7fffffff;
        float s0 = 0.0f, s1 = 0.0f;

        #pragma unroll
        for (int i = 0; i < 8; i++) {
            if (i == 7 && !tail) break;
            int idx4 = lane + i * 32;
            float4 v = __ldcs(rp + idx4);
            float qm = fmaxf(fmaxf(v.x, v.y), fmaxf(v.z, v.w));
            if (qm > m) {                        // rare after warmup
                float resc = exp2f((m - qm) * LOG2E_F);  // m=-INF -> 0, s=0 ok
                s0 *= resc; s1 *= resc;
                m   = qm;
                nml = -m * LOG2E_F;
                int base = idx4 * 4;
                am = (v.x == qm) ? base
                   : (v.y == qm) ? base + 1
                   : (v.z == qm) ? base + 2 : base + 3;
            }
            s0 += exp2f(fmaf(v.x, LOG2E_F, nml));
            s1 += exp2f(fmaf(v.y, LOG2E_F, nml));
            s0 += exp2f(fmaf(v.z, LOG2E_F, nml));
            s1 += exp2f(fmaf(v.w, LOG2E_F, nml));
        }
        float s = s0 + s1;

        // Cross-lane online-softmax merge (strict >, min-index tiebreak).
        #pragma unroll
        for (int off = 16; off; off >>= 1) {
            float om = __shfl_xor_sync(0xffffffffu, m,  off);
            float os = __shfl_xor_sync(0xffffffffu, s,  off);
            int   oa = __shfl_xor_sync(0xffffffffu, am, off);
            float nm = fmaxf(m, om);
            s = s  * exp2f((m  - nm) * LOG2E_F)
              + os * exp2f((om - nm) * LOG2E_F);
            if (om > m || (om == m && oa < am)) am = oa;
            m = nm;
        }

        if (lane == 0) {
            float glp = xt - m - __logf(s);
            int idx = t * C_CLS + am;
            g_pair[row_i] = make_float2(glp, __int_as_float(idx));
            atomicAdd(&g_counts[idx], 1);
        }
    }
}

// ---------------------------------------------------------------------------
// k2: one block per class row, one float4/int4 per thread (250 active).
// cmn = (cost+counts) * beta / max(1, rowsum); zeroes counts row for the
// next call (block-local -> race-free).
// ---------------------------------------------------------------------------
__global__ __launch_bounds__(256) void k_scale(const float* __restrict__ cost) {
    int r  = blockIdx.x;
    int c4 = threadIdx.x;
    float4 res = make_float4(0.f, 0.f, 0.f, 0.f);
    float  s   = 0.0f;
    if (c4 < C4) {
        float4 cv = *(const float4*)(cost + (size_t)r * C_CLS + c4 * 4);
        int4   nv = *(const int4*)(g_counts + (size_t)r * C_CLS + c4 * 4);
        res.x = cv.x + (float)nv.x;
        res.y = cv.y + (float)nv.y;
        res.z = cv.z + (float)nv.z;
        res.w = cv.w + (float)nv.w;
        s = (res.x + res.y) + (res.z + res.w);
    }
    __shared__ float sh[256];
    sh[threadIdx.x] = s;
    __syncthreads();
    #pragma unroll
    for (int off = 128; off; off >>= 1) {
        if (threadIdx.x < off) sh[threadIdx.x] += sh[threadIdx.x + off];
        __syncthreads();
    }
    float scale = BETA_F / fmaxf(1.0f, sh[0]);
    if (c4 < C4) {
        *(float4*)(g_cmn + (size_t)r * C_CLS + c4 * 4) =
            make_float4(res.x * scale, res.y * scale,
                        res.z * scale, res.w * scale);
        *(int4*)(g_counts + (size_t)r * C_CLS + c4 * 4) = make_int4(0, 0, 0, 0);
    }
}

// ---------------------------------------------------------------------------
// k3: per-sample gather + product (1 coalesced float2 + 1 L2 gather),
// warp-shuffle reduce -> partials; fenced last block finishes the
// deterministic tree sum, writes -mean, resets g_done for the next replay.
// ---------------------------------------------------------------------------
__global__ __launch_bounds__(256) void k_dot(float* __restrict__ out) {
    int b = blockIdx.x * 256 + threadIdx.x;
    float2 pr = g_pair[b];                       // exactly B_ROWS threads
    float acc = pr.x * g_cmn[__float_as_int(pr.y)];

    #pragma unroll
    for (int off = 16; off; off >>= 1)
        acc += __shfl_xor_sync(0xffffffffu, acc, off);

    __shared__ float shw[8];
    __shared__ bool  is_last;
    int wid = threadIdx.x >> 5;
    if ((threadIdx.x & 31) == 0) shw[wid] = acc;
    __syncthreads();
    if (threadIdx.x == 0) {
        float sB = ((shw[0] + shw[1]) + (shw[2] + shw[3]))
                 + ((shw[4] + shw[5]) + (shw[6] + shw[7]));
        g_partial[blockIdx.x] = sB;
        __threadfence();
        unsigned done = atomicAdd(&g_done, 1u);
        is_last = (done == (unsigned)(DOT_BLOCKS - 1));
    }
    __syncthreads();

    if (is_last) {
        __shared__ float sh[DOT_BLOCKS];
        sh[threadIdx.x] = g_partial[threadIdx.x];
        __syncthreads();
        #pragma unroll
        for (int off = DOT_BLOCKS / 2; off; off >>= 1) {
            if (threadIdx.x < off) sh[threadIdx.x] += sh[threadIdx.x + off];
            __syncthreads();
        }
        if (threadIdx.x == 0) {
            out[0] = -sh[0] / (float)B_ROWS;
            g_done = 0u;                          // ready for next replay
        }
    }
}

extern "C" void kernel_launch(void* const* d_in, const int* in_sizes, int n_in,
                              void* d_out, int out_size) {
    const float* outputs = (const float*)d_in[0];
    const void*  targets = d_in[1];
    const float* cost    = (const float*)d_in[2];
    float* out = (float*)d_out;

    k_rows <<<ROWS_BLOCKS, 256>>>(outputs, targets);  // persistent, 6/SM
    k_scale<<<C_CLS, 256>>>(cost);
    k_dot  <<<DOT_BLOCKS, 256>>>(out);
}

// round 13
// speedup vs baseline: 1.1983x; 1.1983x over previous
#include <cuda_runtime.h>
#include <math.h>

#define B_ROWS 65536
#define C_CLS  1000
#define C4     250        // 1000 floats = 250 float4 per row
#define BETA_F 3.0f
#define LOG2E_F 1.4426950408889634f
#define DOT_BLOCKS 256
#define ROWS_BLOCKS 888   // 6 blocks/SM * 148 SMs -> single persistent wave
#define ROWS_WARPS (ROWS_BLOCKS * 8)
#define CNT4 (C_CLS * C_CLS / 4)   // counts matrix in int4 units

// ---- scratch (no allocations allowed; zero-initialized at module load) ----
__device__ __align__(16) int    g_counts[C_CLS * C_CLS];
__device__ int    g_hist[C_CLS];              // histogram of targets
__device__ float  g_scale[C_CLS];             // beta / max(1, rowsum)
__device__ __align__(16) float2 g_pair[B_ROWS];  // {glp, bits(t*1000+p)}
__device__ float  g_partial[DOT_BLOCKS];
__device__ unsigned int g_sync1, g_sync2;     // k_dot barriers (self-resetting)

// ---------------------------------------------------------------------------
// k1 (= R11 two-pass, proven best): PERSISTENT one-warp-per-row, 6 blocks/SM.
// Pass 1: FMNMX-only max (front-batched LDG.128, fills L1). Pass 2: L1
// re-read (.cs) -> sumexp + argmax-by-equality (min index of v==m, exact
// bits = first-index jnp.argmax). Extra vs R11: hist[t] atomic for rowsums.
// ---------------------------------------------------------------------------
__global__ __launch_bounds__(256, 6) void k_rows(
    const float* __restrict__ outp, const void* __restrict__ tgt)
{
    int tid   = threadIdx.x;
    int lane  = tid & 31;
    int gwarp = (blockIdx.x * 256 + tid) >> 5;

    // Per-warp dtype detect (hoisted): int64 targets in [0,1000) have
    // all-zero odd 32-bit words. Scan odd words of the first 64 entries.
    const int* tw = (const int*)tgt;
    int nz = tw[4 * lane + 1] | tw[4 * lane + 3];
    int is64 = (__ballot_sync(0xffffffffu, nz != 0) == 0u);
    const long long* t64 = (const long long*)tgt;
    const int*       t32 = (const int*)tgt;

    bool tail = (lane < (C4 - 224));            // last quad valid?

    for (int row_i = gwarp; row_i < B_ROWS; row_i += ROWS_WARPS) {
        const float*  row = outp + (size_t)row_i * C_CLS;
        const float4* rp  = (const float4*)row;

        // Prefetch target index + target logit on lane 0 (overlaps loads).
        int   t  = 0;
        float xt = 0.0f;
        if (lane == 0) {
            t  = is64 ? (int)t64[row_i] : t32[row_i];
            xt = row[t];
        }

        // Pass 1: row max only (1 FMNMX per element), unconditional body.
        float m = -INFINITY;
        #pragma unroll
        for (int i = 0; i < 7; i++) {
            float4 v = rp[lane + i * 32];
            m = fmaxf(m, fmaxf(fmaxf(v.x, v.y), fmaxf(v.z, v.w)));
        }
        if (tail) {
            float4 v = rp[lane + 224];
            m = fmaxf(m, fmaxf(fmaxf(v.x, v.y), fmaxf(v.z, v.w)));
        }
        #pragma unroll
        for (int off = 16; off; off >>= 1)
            m = fmaxf(m, __shfl_xor_sync(0xffffffffu, m, off));

        // Pass 2: reload from L1 (.cs: last use), sumexp + first max index.
        float nml = -m * LOG2E_F;
        float s0 = 0.f, s1 = 0.f, s2 = 0.f, s3 = 0.f;
        int am = 0x7fffffff;
        #pragma unroll
        for (int i = 0; i < 7; i++) {
            int idx4 = lane + i * 32;
            float4 v = __ldcs(rp + idx4);
            int base = idx4 * 4;
            s0 += exp2f(fmaf(v.x, LOG2E_F, nml));
            s1 += exp2f(fmaf(v.y, LOG2E_F, nml));
            s2 += exp2f(fmaf(v.z, LOG2E_F, nml));
            s3 += exp2f(fmaf(v.w, LOG2E_F, nml));
            if (v.x == m) am = min(am, base + 0);
            if (v.y == m) am = min(am, base + 1);
            if (v.z == m) am = min(am, base + 2);
            if (v.w == m) am = min(am, base + 3);
        }
        if (tail) {
            int idx4 = lane + 224;
            float4 v = __ldcs(rp + idx4);
            int base = idx4 * 4;
            s0 += exp2f(fmaf(v.x, LOG2E_F, nml));
            s1 += exp2f(fmaf(v.y, LOG2E_F, nml));
            s2 += exp2f(fmaf(v.z, LOG2E_F, nml));
            s3 += exp2f(fmaf(v.w, LOG2E_F, nml));
            if (v.x == m) am = min(am, base + 0);
            if (v.y == m) am = min(am, base + 1);
            if (v.z == m) am = min(am, base + 2);
            if (v.w == m) am = min(am, base + 3);
        }
        float s = (s0 + s1) + (s2 + s3);
        #pragma unroll
        for (int off = 16; off; off >>= 1) {
            s  += __shfl_xor_sync(0xffffffffu, s, off);
            am  = min(am, __shfl_xor_sync(0xffffffffu, am, off));
        }

        if (lane == 0) {
            float glp = xt - m - __logf(s);
            int idx = t * C_CLS + am;
            g_pair[row_i] = make_float2(glp, __int_as_float(idx));
            atomicAdd(&g_counts[idx], 1);
            atomicAdd(&g_hist[t], 1);
        }
    }
}

// ---------------------------------------------------------------------------
// k2: one block per class row. rowsum[r] = sum(cost[r,:]) + hist[r]
// (identity: counts row-sum == target histogram). Reads ONLY the 4MB cost
// matrix; writes scale[r]; zeroes hist[r] for the next replay.
// ---------------------------------------------------------------------------
__global__ __launch_bounds__(256) void k_scale(const float* __restrict__ cost) {
    int r  = blockIdx.x;
    int c4 = threadIdx.x;
    float s = 0.0f;
    if (c4 < C4) {
        float4 cv = *(const float4*)(cost + (size_t)r * C_CLS + c4 * 4);
        s = (cv.x + cv.y) + (cv.z + cv.w);
    }
    __shared__ float sh[256];
    sh[threadIdx.x] = s;
    __syncthreads();
    #pragma unroll
    for (int off = 128; off; off >>= 1) {
        if (threadIdx.x < off) sh[threadIdx.x] += sh[threadIdx.x + off];
        __syncthreads();
    }
    if (threadIdx.x == 0) {
        float rowsum = sh[0] + (float)g_hist[r];
        g_scale[r] = BETA_F / fmaxf(1.0f, rowsum);
        g_hist[r]  = 0;                      // ready for next replay
    }
}

// ---------------------------------------------------------------------------
// k3: per-sample gather: (cost[idx]+counts[idx]) * scale[idx/1000] * glp.
// Warp/block reduce -> partials. Then a 256-block co-resident spin barrier
// (all gathers done) -> blocks cooperatively ZERO the counts matrix for the
// next replay; block 0 does the final deterministic tree sum; last arrival
// at the 2nd counter resets both counters.
// ---------------------------------------------------------------------------
__global__ __launch_bounds__(256) void k_dot(
    const float* __restrict__ cost, float* __restrict__ out)
{
    int bid = blockIdx.x, tid = threadIdx.x;
    int b = bid * 256 + tid;                     // exactly B_ROWS threads
    float2 pr = g_pair[b];
    int idx = __float_as_int(pr.y);
    int t   = (int)((unsigned)idx / (unsigned)C_CLS);
    float cm  = cost[idx] + (float)g_counts[idx];
    float acc = pr.x * cm * g_scale[t];

    #pragma unroll
    for (int off = 16; off; off >>= 1)
        acc += __shfl_xor_sync(0xffffffffu, acc, off);

    __shared__ float shw[8];
    if ((tid & 31) == 0) shw[tid >> 5] = acc;
    __syncthreads();                             // all gathers in block done
    if (tid == 0) {
        float sB = ((shw[0] + shw[1]) + (shw[2] + shw[3]))
                 + ((shw[4] + shw[5]) + (shw[6] + shw[7]));
        g_partial[bid] = sB;
        __threadfence();
        atomicAdd(&g_sync1, 1u);
        while (atomicAdd(&g_sync1, 0u) < (unsigned)DOT_BLOCKS) { }
    }
    __syncthreads();                             // ALL blocks' gathers done

    // Cooperative zeroing of counts (4MB) — safe now.
    int4* cz = (int4*)g_counts;
    for (int i = bid * 256 + tid; i < CNT4; i += DOT_BLOCKS * 256)
        cz[i] = make_int4(0, 0, 0, 0);

    // Block 0: final deterministic reduce (partials complete after barrier).
    if (bid == 0) {
        __shared__ float sh[DOT_BLOCKS];
        sh[tid] = g_partial[tid];
        __syncthreads();
        #pragma unroll
        for (int off = DOT_BLOCKS / 2; off; off >>= 1) {
            if (tid < off) sh[tid] += sh[tid + off];
            __syncthreads();
        }
        if (tid == 0) out[0] = -sh[0] / (float)B_ROWS;
    }

    // Reset barrier counters for the next graph replay.
    __syncthreads();
    if (tid == 0) {
        unsigned done = atomicAdd(&g_sync2, 1u);
        if (done == (unsigned)(DOT_BLOCKS - 1)) {
            g_sync1 = 0u;
            g_sync2 = 0u;
        }
    }
}

extern "C" void kernel_launch(void* const* d_in, const int* in_sizes, int n_in,
                              void* d_out, int out_size) {
    const float* outputs = (const float*)d_in[0];
    const void*  targets = d_in[1];
    const float* cost    = (const float*)d_in[2];
    float* out = (float*)d_out;

    k_rows <<<ROWS_BLOCKS, 256>>>(outputs, targets);  // persistent, 6/SM
    k_scale<<<C_CLS, 256>>>(cost);
    k_dot  <<<DOT_BLOCKS, 256>>>(cost, out);
}